// round 1
// baseline (speedup 1.0000x reference)
#include <cuda_runtime.h>
#include <cstdint>

#define L      8192
#define CH     16
#define BATCH  32
#define IGSTC  10
#define TW     512            // tile width (outputs per block)
#define NTILES (L / TW)       // 16
#define NTHREADS 256
#define NSTEPS 100

// shared buffer extents / strides (strides chosen ≡2 mod 4 words -> conflict-free per-cout)
#define ZEXT  552
#define ZS    554
#define K1EXT 544
#define K1S   546
#define K2EXT 528
#define K2S   530
// buffer base positions relative to X0: zb: X0-20, k1: X0-16, k2: X0-8

typedef unsigned long long ull;

__device__ float g_scratch[(size_t)BATCH * CH * L];

__device__ __forceinline__ ull pk2(float lo, float hi) {
    ull r; asm("mov.b64 %0, {%1,%2};" : "=l"(r) : "f"(lo), "f"(hi)); return r;
}
__device__ __forceinline__ void fma2(ull &acc, ull a, ull b) {
    asm("fma.rn.f32x2 %0, %1, %2, %0;" : "+l"(acc) : "l"(a), "l"(b));
}
__device__ __forceinline__ ull mul2(ull a, ull b) {
    ull r; asm("mul.rn.f32x2 %0, %1, %2;" : "=l"(r) : "l"(a), "l"(b)); return r;
}

// conv window for one cin: 12 floats starting at rowp+off (off even).
// acc[j] += sum_t w[t] * in[p0 + 2j + {0,1} + t - 2]
__device__ __forceinline__ void conv_cin(const float* rowp, int off, const ull* wv, ull acc[4]) {
    const float2* z2 = reinterpret_cast<const float2*>(rowp + off);
    float2 f0 = z2[0], f1 = z2[1], f2 = z2[2], f3 = z2[3], f4 = z2[4], f5 = z2[5];
    ull w0 = wv[0], w1 = wv[1], w2 = wv[2], w3 = wv[3], w4 = wv[4];
    ull a0 = pk2(f0.x, f0.y), a1 = pk2(f1.x, f1.y), a2 = pk2(f2.x, f2.y);
    ull a3 = pk2(f3.x, f3.y), a4 = pk2(f4.x, f4.y), a5 = pk2(f5.x, f5.y);
    ull o0 = pk2(f0.y, f1.x), o1 = pk2(f1.y, f2.x), o2 = pk2(f2.y, f3.x);
    ull o3 = pk2(f3.y, f4.x), o4 = pk2(f4.y, f5.x);
    fma2(acc[0], a0, w0); fma2(acc[0], o0, w1); fma2(acc[0], a1, w2); fma2(acc[0], o1, w3); fma2(acc[0], a2, w4);
    fma2(acc[1], a1, w0); fma2(acc[1], o1, w1); fma2(acc[1], a2, w2); fma2(acc[1], o2, w3); fma2(acc[1], a3, w4);
    fma2(acc[2], a2, w0); fma2(acc[2], o2, w1); fma2(acc[2], a3, w2); fma2(acc[2], o3, w3); fma2(acc[2], a4, w4);
    fma2(acc[3], a3, w0); fma2(acc[3], o3, w1); fma2(acc[3], a4, w2); fma2(acc[3], o4, w3); fma2(acc[3], a5, w4);
}

// ghost/pad fixup on a stage buffer (boundary tiles only)
__device__ __forceinline__ void fixup(float* buf, int stride, int extent, int basepos) {
    for (int i = threadIdx.x; i < CH * extent; i += NTHREADS) {
        int c = i / extent, idx = i - c * extent;
        int gp = basepos + idx;
        float v;
        if (gp < 0 || gp >= L) {
            v = 0.0f;
        } else {
            int q = gp < IGSTC ? IGSTC : (gp > L - 1 - IGSTC ? L - 1 - IGSTC : gp);
            if (q == gp) continue;
            v = buf[c * stride + (q - basepos)];
        }
        buf[c * stride + idx] = v;
    }
}

__global__ void __launch_bounds__(NTHREADS, 2)
rk3_step_kernel(const float* __restrict__ src_ext, float* __restrict__ dst_ext,
                const float* __restrict__ W, int src_sel, int dst_sel) {
    extern __shared__ float sm[];
    float*  zb = sm;                        // CH * ZS
    float*  k1 = zb + CH * ZS;              // CH * K1S
    float*  k2 = k1 + CH * K1S;             // CH * K2S
    float2* wd = (float2*)(k2 + CH * K2S);  // [16][81] duplicated weights

    const int tid  = threadIdx.x;
    const int tile = blockIdx.x;
    const int b    = blockIdx.y;
    const int X0   = tile * TW;
    const bool bdry = (tile == 0) || (tile == NTILES - 1);
    const int cout = tid & 15;
    const int slot = tid >> 4;

    const float* src = src_sel ? g_scratch : src_ext;
    float*       dst = dst_sel ? g_scratch : dst_ext;

    // duplicated weights into smem: wd[cout][cin*5+t] = (w,w); padded row stride 81
    for (int i = tid; i < CH * CH * 5; i += NTHREADS) {
        int co = i / 80, r = i - co * 80;
        float w = W[i];
        wd[co * 81 + r] = make_float2(w, w);
    }
    // load z tile (+halo, global zero-pad)
    const float* srcb = src + (size_t)b * CH * L;
    for (int i = tid; i < CH * ZEXT; i += NTHREADS) {
        int c = i / ZEXT, idx = i - c * ZEXT;
        int gp = X0 - 20 + idx;
        zb[c * ZS + idx] = (gp >= 0 && gp < L) ? srcb[c * L + gp] : 0.0f;
    }
    __syncthreads();

    const ull* wrowu = (const ull*)&wd[cout * 81];
    const float h = 0.01f;
    const ull hdup  = pk2(h, h);
    const ull qdup  = pk2(0.25f, 0.25f);
    const ull qhdup = pk2(0.25f * h, 0.25f * h);
    const ull tqdup = pk2(0.75f, 0.75f);
    const ull c13   = pk2(1.0f / 3.0f, 1.0f / 3.0f);
    const ull c23   = pk2(2.0f / 3.0f, 2.0f / 3.0f);
    const ull c2h3  = pk2(2.0f * h / 3.0f, 2.0f * h / 3.0f);

    // ---- stage 1: k1 = B(z + h*conv(z)); compute on [X0-16, X0+TW+16), 68 chunks
    for (int c = slot; c < 68; c += 16) {
        ull acc[4] = {0ull, 0ull, 0ull, 0ull};
        #pragma unroll
        for (int cin = 0; cin < 16; ++cin)
            conv_cin(zb + cin * ZS, 8 * c + 2, wrowu + cin * 5, acc);
        #pragma unroll
        for (int j = 0; j < 4; ++j) {
            ull r = *(const ull*)(zb + cout * ZS + 8 * c + 4 + 2 * j);
            fma2(r, acc[j], hdup);                      // r = z + h*conv
            *(ull*)(k1 + cout * K1S + 8 * c + 2 * j) = r;
        }
    }
    __syncthreads();
    if (bdry) { fixup(k1, K1S, K1EXT, X0 - 16); __syncthreads(); }

    // ---- stage 2: k2 = B(0.75 z + 0.25 k1 + 0.25 h conv(k1)); [X0-8, X0+TW+8), 66 chunks
    for (int c = slot; c < 66; c += 16) {
        ull acc[4] = {0ull, 0ull, 0ull, 0ull};
        #pragma unroll
        for (int cin = 0; cin < 16; ++cin)
            conv_cin(k1 + cin * K1S, 8 * c + 6, wrowu + cin * 5, acc);
        #pragma unroll
        for (int j = 0; j < 4; ++j) {
            ull k1p = *(const ull*)(k1 + cout * K1S + 8 * c + 8 + 2 * j);
            ull zp  = *(const ull*)(zb + cout * ZS  + 8 * c + 12 + 2 * j);
            ull r = mul2(acc[j], qhdup);
            fma2(r, k1p, qdup);
            fma2(r, zp, tqdup);
            *(ull*)(k2 + cout * K2S + 8 * c + 2 * j) = r;
        }
    }
    __syncthreads();
    if (bdry) { fixup(k2, K2S, K2EXT, X0 - 8); __syncthreads(); }

    // ---- stage 3: z_new = B(z/3 + 2 k2/3 + 2h conv(k2)/3); [X0, X0+TW), 64 chunks
    float* dstb = dst + (size_t)b * CH * L;
    for (int c = slot; c < 64; c += 16) {
        ull acc[4] = {0ull, 0ull, 0ull, 0ull};
        #pragma unroll
        for (int cin = 0; cin < 16; ++cin)
            conv_cin(k2 + cin * K2S, 8 * c + 6, wrowu + cin * 5, acc);
        #pragma unroll
        for (int j = 0; j < 4; ++j) {
            ull k2p = *(const ull*)(k2 + cout * K2S + 8 * c + 8 + 2 * j);
            ull zp  = *(const ull*)(zb + cout * ZS  + 8 * c + 20 + 2 * j);
            ull r = mul2(acc[j], c2h3);
            fma2(r, k2p, c23);
            fma2(r, zp, c13);
            if (!bdry) {
                *(ull*)(dstb + (size_t)cout * L + X0 + 8 * c + 2 * j) = r;
            } else {
                *(ull*)(k1 + cout * K1S + 8 * c + 16 + 2 * j) = r;  // k1 dead; stash raw3
            }
        }
    }
    if (bdry) {
        __syncthreads();
        for (int i = tid; i < CH * TW; i += NTHREADS) {
            int c = i / TW, idx = i - c * TW;
            int gp = X0 + idx;
            int q = gp < IGSTC ? IGSTC : (gp > L - 1 - IGSTC ? L - 1 - IGSTC : gp);
            dstb[(size_t)c * L + gp] = k1[c * K1S + (q - (X0 - 16))];
        }
    }
}

extern "C" void kernel_launch(void* const* d_in, const int* in_sizes, int n_in,
                              void* d_out, int out_size) {
    const float* z0 = (const float*)d_in[0];
    const float* W  = (const float*)d_in[1];
    float* out = (float*)d_out;

    const size_t smem_bytes =
        (size_t)(CH * (ZS + K1S + K2S) + 16 * 81 * 2) * sizeof(float);  // ~112 KB
    cudaFuncSetAttribute(rk3_step_kernel,
                         cudaFuncAttributeMaxDynamicSharedMemorySize, (int)smem_bytes);

    dim3 grid(NTILES, BATCH);
    for (int s = 0; s < NSTEPS; ++s) {
        // step 0: z0(ext) -> scratch; odd steps -> out; even steps (>=2): out -> scratch
        int src_sel, dst_sel;
        const float* src_ext = nullptr;
        float* dst_ext = nullptr;
        if (s == 0)           { src_sel = 0; src_ext = z0;  dst_sel = 1; }
        else if (s & 1)       { src_sel = 1;                dst_sel = 0; dst_ext = out; }
        else                  { src_sel = 0; src_ext = out; dst_sel = 1; }
        rk3_step_kernel<<<grid, NTHREADS, smem_bytes>>>(src_ext, dst_ext, W, src_sel, dst_sel);
    }
}